// round 3
// baseline (speedup 1.0000x reference)
#include <cuda_runtime.h>

// Problem constants (fixed by the dataset)
#define NN        100000
#define NE        3200000
#define INC       512
#define HID       256
#define OUTC      64
#define NBLK_SCAN 98      // ceil(NN / 1024)

// ---------------- scratch (static __device__ — no allocations) ----------------
__device__ float g_hidden[(size_t)NN * HID];   // 102.4 MB
__device__ float g_h0[(size_t)NN * OUTC];      // 25.6 MB
__device__ float g_hA[(size_t)NN * OUTC];
__device__ float g_hB[(size_t)NN * OUTC];
__device__ int   g_cnt[NN];
__device__ int   g_rowptr[NN + 1];
__device__ int   g_fillpos[NN];
__device__ float g_dinv[NN];
__device__ int   g_col[NE];                    // 12.8 MB
__device__ float g_w[NE];                      // 12.8 MB
__device__ int   g_bsums[NBLK_SCAN];

// ---------------- graph preprocessing ----------------
__global__ void k_zero_cnt() {
    int i = blockIdx.x * blockDim.x + threadIdx.x;
    if (i < NN) g_cnt[i] = 0;
}

// ei is int32 (JAX default x64-disabled downgrades int64 -> int32)
__global__ void k_count(const int* __restrict__ ei) {
    int e = blockIdx.x * blockDim.x + threadIdx.x;
    if (e < NE) {
        int d = ei[NE + e];
        if (d >= 0 && d < NN) atomicAdd(&g_cnt[d], 1);
    }
}

__global__ void k_dinv() {
    int i = blockIdx.x * blockDim.x + threadIdx.x;
    if (i < NN) g_dinv[i] = rsqrtf((float)(g_cnt[i] + 1)); // +1 self loop
}

// block-level inclusive scan of g_cnt -> g_rowptr (temp), block totals -> g_bsums
__global__ void k_scan1() {
    __shared__ int s[1024];
    int tid = threadIdx.x;
    int i = blockIdx.x * 1024 + tid;
    int v = (i < NN) ? g_cnt[i] : 0;
    s[tid] = v;
    __syncthreads();
    for (int off = 1; off < 1024; off <<= 1) {
        int t = (tid >= off) ? s[tid - off] : 0;
        __syncthreads();
        s[tid] += t;
        __syncthreads();
    }
    if (i < NN) g_rowptr[i] = s[tid];
    if (tid == 1023) g_bsums[blockIdx.x] = s[1023];
}

__global__ void k_scan2() {
    if (threadIdx.x == 0) {
        int run = 0;
        for (int b = 0; b < NBLK_SCAN; b++) { int t = g_bsums[b]; g_bsums[b] = run; run += t; }
    }
}

__global__ void k_scan3() {
    int i = blockIdx.x * blockDim.x + threadIdx.x;
    if (i < NN) {
        int ex = g_rowptr[i] - g_cnt[i] + g_bsums[i >> 10]; // global exclusive
        g_rowptr[i]  = ex;
        g_fillpos[i] = ex;
    }
    if (i == 0) g_rowptr[NN] = NE;
}

__global__ void k_fill(const int* __restrict__ ei) {
    int e = blockIdx.x * blockDim.x + threadIdx.x;
    if (e < NE) {
        int s = ei[e];
        int d = ei[NE + e];
        if (s >= 0 && s < NN && d >= 0 && d < NN) {
            int p = atomicAdd(&g_fillpos[d], 1);
            g_col[p] = s;
            g_w[p]   = g_dinv[s] * g_dinv[d];
        }
    }
}

// ---------------- fp32 SIMT GEMM: C = act(A @ B + bias) ----------------
// 64x64 block tile, 16x16 threads, 4x4 microtile, BK=16
// MODE 0: A = x (param), C = g_hidden, relu
// MODE 1: A = g_hidden,  C = g_h0, no relu
template <int MODE>
__global__ void __launch_bounds__(256) k_gemm(
    const float* __restrict__ Ain, const float* __restrict__ B,
    const float* __restrict__ bias,
    int M, int N, int K)
{
    const float* A = (MODE == 0) ? Ain : (const float*)g_hidden;
    float* C = (MODE == 0) ? (float*)g_hidden : (float*)g_h0;

    const int BK = 16;
    __shared__ float As[BK][68];  // As[k][m] (transposed on load)
    __shared__ float Bs[BK][68];

    int tid = threadIdx.x;
    int tx = tid & 15, ty = tid >> 4;
    int row0 = blockIdx.x * 64;
    int col0 = blockIdx.y * 64;

    int la_m = tid >> 2;          // 0..63
    int la_k = (tid & 3) << 2;    // 0,4,8,12
    int lb_k = tid >> 4;          // 0..15
    int lb_n = (tid & 15) << 2;   // 0..60

    const float* Aptr = A + (size_t)(row0 + la_m) * K + la_k;
    bool arow_ok = (row0 + la_m) < M;
    const float* Bptr = B + (size_t)lb_k * N + col0 + lb_n;

    float acc[4][4] = {};

    for (int k0 = 0; k0 < K; k0 += BK) {
        float4 av = make_float4(0.f, 0.f, 0.f, 0.f);
        if (arow_ok) av = *(const float4*)(Aptr + k0);
        As[la_k + 0][la_m] = av.x;
        As[la_k + 1][la_m] = av.y;
        As[la_k + 2][la_m] = av.z;
        As[la_k + 3][la_m] = av.w;
        *(float4*)&Bs[lb_k][lb_n] = *(const float4*)(Bptr + (size_t)k0 * N);
        __syncthreads();
#pragma unroll
        for (int k = 0; k < BK; k++) {
            float4 a = *(const float4*)&As[k][ty << 2];
            float4 b = *(const float4*)&Bs[k][tx << 2];
            acc[0][0] = fmaf(a.x, b.x, acc[0][0]); acc[0][1] = fmaf(a.x, b.y, acc[0][1]);
            acc[0][2] = fmaf(a.x, b.z, acc[0][2]); acc[0][3] = fmaf(a.x, b.w, acc[0][3]);
            acc[1][0] = fmaf(a.y, b.x, acc[1][0]); acc[1][1] = fmaf(a.y, b.y, acc[1][1]);
            acc[1][2] = fmaf(a.y, b.z, acc[1][2]); acc[1][3] = fmaf(a.y, b.w, acc[1][3]);
            acc[2][0] = fmaf(a.z, b.x, acc[2][0]); acc[2][1] = fmaf(a.z, b.y, acc[2][1]);
            acc[2][2] = fmaf(a.z, b.z, acc[2][2]); acc[2][3] = fmaf(a.z, b.w, acc[2][3]);
            acc[3][0] = fmaf(a.w, b.x, acc[3][0]); acc[3][1] = fmaf(a.w, b.y, acc[3][1]);
            acc[3][2] = fmaf(a.w, b.z, acc[3][2]); acc[3][3] = fmaf(a.w, b.w, acc[3][3]);
        }
        __syncthreads();
    }

    float4 bb = *(const float4*)&bias[col0 + (tx << 2)];
#pragma unroll
    for (int i = 0; i < 4; i++) {
        int r = row0 + (ty << 2) + i;
        if (r < M) {
            float4 o;
            o.x = acc[i][0] + bb.x;
            o.y = acc[i][1] + bb.y;
            o.z = acc[i][2] + bb.z;
            o.w = acc[i][3] + bb.w;
            if (MODE == 0) {
                o.x = fmaxf(o.x, 0.f); o.y = fmaxf(o.y, 0.f);
                o.z = fmaxf(o.z, 0.f); o.w = fmaxf(o.w, 0.f);
            }
            *(float4*)&C[(size_t)r * N + col0 + (tx << 2)] = o;
        }
    }
}

// ---------------- propagation: hout = 0.9 * (P @ hin) + 0.1 * h0 ----------------
// one warp per dst node; lane l handles columns 2l, 2l+1
// Buffer ids: 0 = g_h0, 1 = g_hA, 2 = g_hB, 3 = external out (param)
__global__ void __launch_bounds__(256) k_prop(int src_id, int dst_id,
                                              float* __restrict__ ext_out)
{
    const float* hin = (src_id == 0) ? (const float*)g_h0
                     : (src_id == 1) ? (const float*)g_hA
                                     : (const float*)g_hB;
    float* hout = (dst_id == 1) ? (float*)g_hA
                : (dst_id == 2) ? (float*)g_hB
                                : ext_out;

    int node = (blockIdx.x * blockDim.x + threadIdx.x) >> 5;
    int lane = threadIdx.x & 31;
    if (node >= NN) return;
    int beg = g_rowptr[node];
    int end = g_rowptr[node + 1];
    int c0 = lane << 1;
    float ax = 0.f, ay = 0.f;
    for (int base = beg; base < end; base += 32) {
        int nb = end - base; if (nb > 32) nb = 32;
        int src = 0; float wt = 0.f;
        if (lane < nb) { src = g_col[base + lane]; wt = g_w[base + lane]; }
        for (int j = 0; j < nb; j++) {
            int   s  = __shfl_sync(0xffffffffu, src, j);
            float ww = __shfl_sync(0xffffffffu, wt, j);
            float2 hv = *(const float2*)(hin + (size_t)s * OUTC + c0);
            ax = fmaf(ww, hv.x, ax);
            ay = fmaf(ww, hv.y, ay);
        }
    }
    // self loop: norm = dinv[node]^2
    float dv = g_dinv[node];
    float sw = dv * dv;
    float2 hs = *(const float2*)(hin + (size_t)node * OUTC + c0);
    ax = fmaf(sw, hs.x, ax);
    ay = fmaf(sw, hs.y, ay);
    float2 h0v = *(const float2*)(g_h0 + (size_t)node * OUTC + c0);
    float2 o;
    o.x = 0.9f * ax + 0.1f * h0v.x;
    o.y = 0.9f * ay + 0.1f * h0v.y;
    *(float2*)(hout + (size_t)node * OUTC + c0) = o;
}

// ---------------- launch ----------------
extern "C" void kernel_launch(void* const* d_in, const int* in_sizes, int n_in,
                              void* d_out, int out_size)
{
    const float* x  = (const float*)d_in[0];
    const int*   ei = (const int*)d_in[1];     // int32 (JAX x64 disabled)
    const float* W1 = (const float*)d_in[2];
    const float* b1 = (const float*)d_in[3];
    const float* W2 = (const float*)d_in[4];
    const float* b2 = (const float*)d_in[5];
    float* out = (float*)d_out;

    // graph preprocessing -> CSR by dst
    k_zero_cnt<<<(NN + 255) / 256, 256>>>();
    k_count<<<(NE + 255) / 256, 256>>>(ei);
    k_dinv<<<(NN + 255) / 256, 256>>>();
    k_scan1<<<NBLK_SCAN, 1024>>>();
    k_scan2<<<1, 32>>>();
    k_scan3<<<(NN + 255) / 256, 256>>>();
    k_fill<<<(NE + 255) / 256, 256>>>(ei);

    // MLP encoder
    dim3 g1((NN + 63) / 64, HID / 64);
    k_gemm<0><<<g1, 256>>>(x, W1, b1, NN, HID, INC);
    dim3 g2((NN + 63) / 64, OUTC / 64);
    k_gemm<1><<<g2, 256>>>(nullptr, W2, b2, NN, OUTC, HID);

    // 10 propagation iterations (ping-pong; last writes d_out)
    int pgrid = (NN * 32 + 255) / 256;
    k_prop<<<pgrid, 256>>>(0, 1, out);
    k_prop<<<pgrid, 256>>>(1, 2, out);
    k_prop<<<pgrid, 256>>>(2, 1, out);
    k_prop<<<pgrid, 256>>>(1, 2, out);
    k_prop<<<pgrid, 256>>>(2, 1, out);
    k_prop<<<pgrid, 256>>>(1, 2, out);
    k_prop<<<pgrid, 256>>>(2, 1, out);
    k_prop<<<pgrid, 256>>>(1, 2, out);
    k_prop<<<pgrid, 256>>>(2, 1, out);
    k_prop<<<pgrid, 256>>>(1, 3, out);
    (void)in_sizes; (void)n_in; (void)out_size;
}

// round 7
// speedup vs baseline: 1.0597x; 1.0597x over previous
#include <cuda_runtime.h>

// Problem constants (fixed by the dataset)
#define NN        100000
#define NE        3200000
#define INC       512
#define HID       256
#define OUTC      64
#define NBLK_SCAN 98      // ceil(NN / 1024)

// ---------------- scratch (static __device__ — no allocations) ----------------
__device__ float g_hidden[(size_t)NN * HID];   // 102.4 MB
__device__ float g_h0[(size_t)NN * OUTC];      // 25.6 MB
__device__ float g_hA[(size_t)NN * OUTC];
__device__ float g_hB[(size_t)NN * OUTC];
__device__ int   g_cnt[NN];
__device__ int   g_rowptr[NN + 1];
__device__ int   g_fillpos[NN];
__device__ float g_dinv[NN];
__device__ int   g_col[NE];                    // 12.8 MB
__device__ float g_w[NE];                      // 12.8 MB
__device__ int   g_bsums[NBLK_SCAN];

// ---------------- graph preprocessing ----------------
__global__ void k_zero_cnt() {
    int i = blockIdx.x * blockDim.x + threadIdx.x;
    if (i < NN) g_cnt[i] = 0;
}

// ei is int32 (JAX default x64-disabled downgrades int64 -> int32)
__global__ void k_count(const int* __restrict__ ei) {
    int e = blockIdx.x * blockDim.x + threadIdx.x;
    if (e < NE) {
        int d = ei[NE + e];
        if (d >= 0 && d < NN) atomicAdd(&g_cnt[d], 1);
    }
}

__global__ void k_dinv() {
    int i = blockIdx.x * blockDim.x + threadIdx.x;
    if (i < NN) g_dinv[i] = rsqrtf((float)(g_cnt[i] + 1)); // +1 self loop
}

// block-level inclusive scan of g_cnt -> g_rowptr (temp), block totals -> g_bsums
__global__ void k_scan1() {
    __shared__ int s[1024];
    int tid = threadIdx.x;
    int i = blockIdx.x * 1024 + tid;
    int v = (i < NN) ? g_cnt[i] : 0;
    s[tid] = v;
    __syncthreads();
    for (int off = 1; off < 1024; off <<= 1) {
        int t = (tid >= off) ? s[tid - off] : 0;
        __syncthreads();
        s[tid] += t;
        __syncthreads();
    }
    if (i < NN) g_rowptr[i] = s[tid];
    if (tid == 1023) g_bsums[blockIdx.x] = s[1023];
}

__global__ void k_scan2() {
    if (threadIdx.x == 0) {
        int run = 0;
        for (int b = 0; b < NBLK_SCAN; b++) { int t = g_bsums[b]; g_bsums[b] = run; run += t; }
    }
}

__global__ void k_scan3() {
    int i = blockIdx.x * blockDim.x + threadIdx.x;
    if (i < NN) {
        int ex = g_rowptr[i] - g_cnt[i] + g_bsums[i >> 10]; // global exclusive
        g_rowptr[i]  = ex;
        g_fillpos[i] = ex;
    }
    if (i == 0) g_rowptr[NN] = NE;
}

__global__ void k_fill(const int* __restrict__ ei) {
    int e = blockIdx.x * blockDim.x + threadIdx.x;
    if (e < NE) {
        int s = ei[e];
        int d = ei[NE + e];
        if (s >= 0 && s < NN && d >= 0 && d < NN) {
            int p = atomicAdd(&g_fillpos[d], 1);
            g_col[p] = s;
            g_w[p]   = g_dinv[s] * g_dinv[d];
        }
    }
}

// ---------------- big fp32 SIMT GEMM: 128x128 tile, 8x8 microtile, BK=8 ----------------
// MODE 0: A = x (param), C = g_hidden, relu.  N must be a multiple of 128, K of 8.
template <int MODE>
__global__ void __launch_bounds__(256) k_gemm128(
    const float* __restrict__ Ain, const float* __restrict__ B,
    const float* __restrict__ bias,
    int M, int N, int K)
{
    const float* A = (MODE == 0) ? Ain : (const float*)g_hidden;
    float* C = (MODE == 0) ? (float*)g_hidden : (float*)g_h0;

    __shared__ float As[8][132];   // transposed A tile [k][m]
    __shared__ float Bs[8][128];   // B tile [k][n]

    int tid = threadIdx.x;
    int tx = tid & 15, ty = tid >> 4;
    int row0 = blockIdx.x * 128;
    int col0 = blockIdx.y * 128;

    // loaders
    int arow = tid >> 1;            // 0..127
    int acol = (tid & 1) << 2;      // 0 or 4
    int brow = tid >> 5;            // 0..7
    int bcol = (tid & 31) << 2;     // 0..124

    const float* Aptr = A + (size_t)(row0 + arow) * K + acol;
    bool arow_ok = (row0 + arow) < M;
    const float* Bptr = B + (size_t)brow * N + col0 + bcol;

    float acc[8][8] = {};

    float4 av = make_float4(0.f, 0.f, 0.f, 0.f);
    if (arow_ok) av = *(const float4*)(Aptr);
    float4 bv = *(const float4*)(Bptr);

    for (int k0 = 0; k0 < K; k0 += 8) {
        As[acol + 0][arow] = av.x;
        As[acol + 1][arow] = av.y;
        As[acol + 2][arow] = av.z;
        As[acol + 3][arow] = av.w;
        *(float4*)&Bs[brow][bcol] = bv;
        __syncthreads();

        if (k0 + 8 < K) {
            av = make_float4(0.f, 0.f, 0.f, 0.f);
            if (arow_ok) av = *(const float4*)(Aptr + k0 + 8);
            bv = *(const float4*)(Bptr + (size_t)(k0 + 8) * N);
        }

#pragma unroll
        for (int k = 0; k < 8; k++) {
            float4 a0 = *(const float4*)&As[k][ty << 3];
            float4 a1 = *(const float4*)&As[k][(ty << 3) + 4];
            float4 b0 = *(const float4*)&Bs[k][tx << 3];
            float4 b1 = *(const float4*)&Bs[k][(tx << 3) + 4];
            float ar[8] = {a0.x, a0.y, a0.z, a0.w, a1.x, a1.y, a1.z, a1.w};
            float br[8] = {b0.x, b0.y, b0.z, b0.w, b1.x, b1.y, b1.z, b1.w};
#pragma unroll
            for (int i = 0; i < 8; i++)
#pragma unroll
                for (int j = 0; j < 8; j++)
                    acc[i][j] = fmaf(ar[i], br[j], acc[i][j]);
        }
        __syncthreads();
    }

    float4 bb0 = *(const float4*)&bias[col0 + (tx << 3)];
    float4 bb1 = *(const float4*)&bias[col0 + (tx << 3) + 4];
    float bbr[8] = {bb0.x, bb0.y, bb0.z, bb0.w, bb1.x, bb1.y, bb1.z, bb1.w};
#pragma unroll
    for (int i = 0; i < 8; i++) {
        int r = row0 + (ty << 3) + i;
        if (r < M) {
            float o[8];
#pragma unroll
            for (int j = 0; j < 8; j++) {
                o[j] = acc[i][j] + bbr[j];
                if (MODE == 0) o[j] = fmaxf(o[j], 0.f);
            }
            float* Cp = &C[(size_t)r * N + col0 + (tx << 3)];
            *(float4*)Cp       = make_float4(o[0], o[1], o[2], o[3]);
            *(float4*)(Cp + 4) = make_float4(o[4], o[5], o[6], o[7]);
        }
    }
}

// ---------------- small fp32 SIMT GEMM: 64x64 tile, 4x4 microtile (for N=64) --------
// MODE 1: A = g_hidden, C = g_h0, no relu
template <int MODE>
__global__ void __launch_bounds__(256) k_gemm(
    const float* __restrict__ Ain, const float* __restrict__ B,
    const float* __restrict__ bias,
    int M, int N, int K)
{
    const float* A = (MODE == 0) ? Ain : (const float*)g_hidden;
    float* C = (MODE == 0) ? (float*)g_hidden : (float*)g_h0;

    const int BK = 16;
    __shared__ float As[BK][68];
    __shared__ float Bs[BK][68];

    int tid = threadIdx.x;
    int tx = tid & 15, ty = tid >> 4;
    int row0 = blockIdx.x * 64;
    int col0 = blockIdx.y * 64;

    int la_m = tid >> 2;
    int la_k = (tid & 3) << 2;
    int lb_k = tid >> 4;
    int lb_n = (tid & 15) << 2;

    const float* Aptr = A + (size_t)(row0 + la_m) * K + la_k;
    bool arow_ok = (row0 + la_m) < M;
    const float* Bptr = B + (size_t)lb_k * N + col0 + lb_n;

    float acc[4][4] = {};

    for (int k0 = 0; k0 < K; k0 += BK) {
        float4 av = make_float4(0.f, 0.f, 0.f, 0.f);
        if (arow_ok) av = *(const float4*)(Aptr + k0);
        As[la_k + 0][la_m] = av.x;
        As[la_k + 1][la_m] = av.y;
        As[la_k + 2][la_m] = av.z;
        As[la_k + 3][la_m] = av.w;
        *(float4*)&Bs[lb_k][lb_n] = *(const float4*)(Bptr + (size_t)k0 * N);
        __syncthreads();
#pragma unroll
        for (int k = 0; k < BK; k++) {
            float4 a = *(const float4*)&As[k][ty << 2];
            float4 b = *(const float4*)&Bs[k][tx << 2];
            acc[0][0] = fmaf(a.x, b.x, acc[0][0]); acc[0][1] = fmaf(a.x, b.y, acc[0][1]);
            acc[0][2] = fmaf(a.x, b.z, acc[0][2]); acc[0][3] = fmaf(a.x, b.w, acc[0][3]);
            acc[1][0] = fmaf(a.y, b.x, acc[1][0]); acc[1][1] = fmaf(a.y, b.y, acc[1][1]);
            acc[1][2] = fmaf(a.y, b.z, acc[1][2]); acc[1][3] = fmaf(a.y, b.w, acc[1][3]);
            acc[2][0] = fmaf(a.z, b.x, acc[2][0]); acc[2][1] = fmaf(a.z, b.y, acc[2][1]);
            acc[2][2] = fmaf(a.z, b.z, acc[2][2]); acc[2][3] = fmaf(a.z, b.w, acc[2][3]);
            acc[3][0] = fmaf(a.w, b.x, acc[3][0]); acc[3][1] = fmaf(a.w, b.y, acc[3][1]);
            acc[3][2] = fmaf(a.w, b.z, acc[3][2]); acc[3][3] = fmaf(a.w, b.w, acc[3][3]);
        }
        __syncthreads();
    }

    float4 bb = *(const float4*)&bias[col0 + (tx << 2)];
#pragma unroll
    for (int i = 0; i < 4; i++) {
        int r = row0 + (ty << 2) + i;
        if (r < M) {
            float4 o;
            o.x = acc[i][0] + bb.x;
            o.y = acc[i][1] + bb.y;
            o.z = acc[i][2] + bb.z;
            o.w = acc[i][3] + bb.w;
            if (MODE == 0) {
                o.x = fmaxf(o.x, 0.f); o.y = fmaxf(o.y, 0.f);
                o.z = fmaxf(o.z, 0.f); o.w = fmaxf(o.w, 0.f);
            }
            *(float4*)&C[(size_t)r * N + col0 + (tx << 2)] = o;
        }
    }
}

// ---------------- propagation: hout = 0.9 * (P @ hin) + 0.1 * h0 ----------------
// one warp per dst node; lane l handles columns 2l, 2l+1
// Buffer ids: 0 = g_h0, 1 = g_hA, 2 = g_hB, 3 = external out (param)
__global__ void __launch_bounds__(256) k_prop(int src_id, int dst_id,
                                              float* __restrict__ ext_out)
{
    const float* hin = (src_id == 0) ? (const float*)g_h0
                     : (src_id == 1) ? (const float*)g_hA
                                     : (const float*)g_hB;
    float* hout = (dst_id == 1) ? (float*)g_hA
                : (dst_id == 2) ? (float*)g_hB
                                : ext_out;

    int node = (blockIdx.x * blockDim.x + threadIdx.x) >> 5;
    int lane = threadIdx.x & 31;
    if (node >= NN) return;
    int beg = g_rowptr[node];
    int end = g_rowptr[node + 1];
    int c0 = lane << 1;
    float ax = 0.f, ay = 0.f;
    for (int base = beg; base < end; base += 32) {
        int nb = end - base; if (nb > 32) nb = 32;
        int src = 0; float wt = 0.f;
        if (lane < nb) { src = g_col[base + lane]; wt = g_w[base + lane]; }
        for (int j = 0; j < nb; j++) {
            int   s  = __shfl_sync(0xffffffffu, src, j);
            float ww = __shfl_sync(0xffffffffu, wt, j);
            float2 hv = *(const float2*)(hin + (size_t)s * OUTC + c0);
            ax = fmaf(ww, hv.x, ax);
            ay = fmaf(ww, hv.y, ay);
        }
    }
    // self loop: norm = dinv[node]^2
    float dv = g_dinv[node];
    float sw = dv * dv;
    float2 hs = *(const float2*)(hin + (size_t)node * OUTC + c0);
    ax = fmaf(sw, hs.x, ax);
    ay = fmaf(sw, hs.y, ay);
    float2 h0v = *(const float2*)(g_h0 + (size_t)node * OUTC + c0);
    float2 o;
    o.x = 0.9f * ax + 0.1f * h0v.x;
    o.y = 0.9f * ay + 0.1f * h0v.y;
    *(float2*)(hout + (size_t)node * OUTC + c0) = o;
}

// ---------------- launch ----------------
extern "C" void kernel_launch(void* const* d_in, const int* in_sizes, int n_in,
                              void* d_out, int out_size)
{
    const float* x  = (const float*)d_in[0];
    const int*   ei = (const int*)d_in[1];     // int32 (JAX x64 disabled)
    const float* W1 = (const float*)d_in[2];
    const float* b1 = (const float*)d_in[3];
    const float* W2 = (const float*)d_in[4];
    const float* b2 = (const float*)d_in[5];
    float* out = (float*)d_out;

    // lazily-created side stream + events for fork-join (created once; never
    // destroyed — a handful of handles, no device memory)
    static cudaStream_t s2 = nullptr;
    static cudaEvent_t evFork = nullptr, evJoin = nullptr;
    if (s2 == nullptr) {
        cudaStreamCreateWithFlags(&s2, cudaStreamNonBlocking);
        cudaEventCreateWithFlags(&evFork, cudaEventDisableTiming);
        cudaEventCreateWithFlags(&evJoin, cudaEventDisableTiming);
    }

    // fork: graph preprocessing -> CSR by dst, on side stream
    cudaEventRecord(evFork, 0);
    cudaStreamWaitEvent(s2, evFork, 0);
    k_zero_cnt<<<(NN + 255) / 256, 256, 0, s2>>>();
    k_count<<<(NE + 255) / 256, 256, 0, s2>>>(ei);
    k_dinv<<<(NN + 255) / 256, 256, 0, s2>>>();
    k_scan1<<<NBLK_SCAN, 1024, 0, s2>>>();
    k_scan2<<<1, 32, 0, s2>>>();
    k_scan3<<<(NN + 255) / 256, 256, 0, s2>>>();
    k_fill<<<(NE + 255) / 256, 256, 0, s2>>>(ei);
    cudaEventRecord(evJoin, s2);

    // MLP encoder on main stream (independent of CSR build)
    dim3 g1((NN + 127) / 128, HID / 128);
    k_gemm128<0><<<g1, 256>>>(x, W1, b1, NN, HID, INC);
    dim3 g2((NN + 63) / 64, OUTC / 64);
    k_gemm<1><<<g2, 256>>>(nullptr, W2, b2, NN, OUTC, HID);

    // join: propagation needs both the CSR and h0
    cudaStreamWaitEvent(0, evJoin, 0);

    // 10 propagation iterations (ping-pong; last writes d_out)
    int pgrid = (NN * 32 + 255) / 256;
    k_prop<<<pgrid, 256>>>(0, 1, out);
    k_prop<<<pgrid, 256>>>(1, 2, out);
    k_prop<<<pgrid, 256>>>(2, 1, out);
    k_prop<<<pgrid, 256>>>(1, 2, out);
    k_prop<<<pgrid, 256>>>(2, 1, out);
    k_prop<<<pgrid, 256>>>(1, 2, out);
    k_prop<<<pgrid, 256>>>(2, 1, out);
    k_prop<<<pgrid, 256>>>(1, 2, out);
    k_prop<<<pgrid, 256>>>(2, 1, out);
    k_prop<<<pgrid, 256>>>(1, 3, out);
    (void)in_sizes; (void)n_in; (void)out_size;
}

// round 8
// speedup vs baseline: 1.3188x; 1.2444x over previous
#include <cuda_runtime.h>
#include <cstdint>

// Problem constants (fixed by the dataset)
#define NN        100000
#define NE        3200000
#define INC       512
#define HID       256
#define OUTC      64
#define NBLK_SCAN 98      // ceil(NN / 1024)

// ---------------- scratch (static __device__ — no allocations) ----------------
__device__ float g_hidden[(size_t)NN * HID];   // 102.4 MB
__device__ float g_h0[(size_t)NN * OUTC];      // 25.6 MB
__device__ float g_hA[(size_t)NN * OUTC];
__device__ float g_hB[(size_t)NN * OUTC];
__device__ int   g_cnt[NN];
__device__ int   g_rowptr[NN + 1];
__device__ int   g_fillpos[NN];
__device__ float g_dinv[NN];
__device__ int2  g_edge[NE];                   // (src, w_bits) 25.6 MB
__device__ int   g_bsums[NBLK_SCAN];

// ---------------- graph preprocessing ----------------
__global__ void k_zero_cnt() {
    int i = blockIdx.x * blockDim.x + threadIdx.x;
    if (i < NN) g_cnt[i] = 0;
}

// ei is int32 (JAX default x64-disabled downgrades int64 -> int32)
__global__ void k_count(const int* __restrict__ ei) {
    int e = blockIdx.x * blockDim.x + threadIdx.x;
    if (e < NE) {
        int d = ei[NE + e];
        if (d >= 0 && d < NN) atomicAdd(&g_cnt[d], 1);
    }
}

__global__ void k_dinv() {
    int i = blockIdx.x * blockDim.x + threadIdx.x;
    if (i < NN) g_dinv[i] = rsqrtf((float)(g_cnt[i] + 1)); // +1 self loop
}

__global__ void k_scan1() {
    __shared__ int s[1024];
    int tid = threadIdx.x;
    int i = blockIdx.x * 1024 + tid;
    int v = (i < NN) ? g_cnt[i] : 0;
    s[tid] = v;
    __syncthreads();
    for (int off = 1; off < 1024; off <<= 1) {
        int t = (tid >= off) ? s[tid - off] : 0;
        __syncthreads();
        s[tid] += t;
        __syncthreads();
    }
    if (i < NN) g_rowptr[i] = s[tid];
    if (tid == 1023) g_bsums[blockIdx.x] = s[1023];
}

__global__ void k_scan2() {
    if (threadIdx.x == 0) {
        int run = 0;
        for (int b = 0; b < NBLK_SCAN; b++) { int t = g_bsums[b]; g_bsums[b] = run; run += t; }
    }
}

__global__ void k_scan3() {
    int i = blockIdx.x * blockDim.x + threadIdx.x;
    if (i < NN) {
        int ex = g_rowptr[i] - g_cnt[i] + g_bsums[i >> 10]; // global exclusive
        g_rowptr[i]  = ex;
        g_fillpos[i] = ex;
    }
    if (i == 0) g_rowptr[NN] = NE;
}

__global__ void k_fill(const int* __restrict__ ei) {
    int e = blockIdx.x * blockDim.x + threadIdx.x;
    if (e < NE) {
        int s = ei[e];
        int d = ei[NE + e];
        if (s >= 0 && s < NN && d >= 0 && d < NN) {
            int p = atomicAdd(&g_fillpos[d], 1);
            float w = g_dinv[s] * g_dinv[d];
            g_edge[p] = make_int2(s, __float_as_int(w));
        }
    }
}

// ---------------- tf32 tensor-core GEMM1: C = relu(A @ B + bias) --------------
// 128x128 tile, BK=16, 8 warps (4m x 2n), warp tile 32x64, mma.m16n8k8 tf32
__device__ __forceinline__ uint32_t f2tf(float f) {
    uint32_t u;
    asm("cvt.rna.tf32.f32 %0, %1;" : "=r"(u) : "f"(f));
    return u;
}

__global__ void __launch_bounds__(256) k_gemm1_tf32(
    const float* __restrict__ A, const float* __restrict__ B,
    const float* __restrict__ bias, int M, int N, int K)
{
    float* C = (float*)g_hidden;
    __shared__ uint32_t As[2][128][20];   // [buf][m][k], stride 20 (conflict-free frag reads)
    __shared__ uint32_t Bs[2][16][136];   // [buf][k][n], stride 136

    int tid = threadIdx.x;
    int lane = tid & 31, wid = tid >> 5;
    int wm = wid & 3, wn = wid >> 2;       // warp tile: rows wm*32, cols wn*64
    int g = lane >> 2, t = lane & 3;
    int row0 = blockIdx.x * 128, col0 = blockIdx.y * 128;

    // cooperative loaders: A tile 128x16 (512 float4), B tile 16x128 (512 float4)
    int ar0 = tid >> 2;            // rows ar0 and ar0+64
    int ac  = (tid & 3) << 2;
    int br0 = tid >> 5;            // rows br0 and br0+8
    int bc  = (tid & 31) << 2;

    const float* Ap0 = A + (size_t)(row0 + ar0) * K + ac;
    const float* Ap1 = A + (size_t)(row0 + ar0 + 64) * K + ac;
    bool aok0 = (row0 + ar0) < M;
    bool aok1 = (row0 + ar0 + 64) < M;
    const float* Bp0 = B + (size_t)br0 * N + col0 + bc;
    const float* Bp1 = B + (size_t)(br0 + 8) * N + col0 + bc;

    float c[2][8][4] = {};

    const float4 fz = make_float4(0.f, 0.f, 0.f, 0.f);
    float4 av0 = aok0 ? *(const float4*)Ap0 : fz;
    float4 av1 = aok1 ? *(const float4*)Ap1 : fz;
    float4 bv0 = *(const float4*)Bp0;
    float4 bv1 = *(const float4*)Bp1;

    int nk = K >> 4;   // 32
    for (int kt = 0; kt < nk; kt++) {
        int cur = kt & 1;
        // store staged regs -> smem[cur]
        *(uint4*)&As[cur][ar0][ac]      = make_uint4(f2tf(av0.x), f2tf(av0.y), f2tf(av0.z), f2tf(av0.w));
        *(uint4*)&As[cur][ar0 + 64][ac] = make_uint4(f2tf(av1.x), f2tf(av1.y), f2tf(av1.z), f2tf(av1.w));
        *(uint4*)&Bs[cur][br0][bc]      = make_uint4(f2tf(bv0.x), f2tf(bv0.y), f2tf(bv0.z), f2tf(bv0.w));
        *(uint4*)&Bs[cur][br0 + 8][bc]  = make_uint4(f2tf(bv1.x), f2tf(bv1.y), f2tf(bv1.z), f2tf(bv1.w));
        __syncthreads();

        if (kt + 1 < nk) {
            int ko = (kt + 1) << 4;
            av0 = aok0 ? *(const float4*)(Ap0 + ko) : fz;
            av1 = aok1 ? *(const float4*)(Ap1 + ko) : fz;
            bv0 = *(const float4*)(Bp0 + (size_t)ko * N);
            bv1 = *(const float4*)(Bp1 + (size_t)ko * N);
        }

#pragma unroll
        for (int ks = 0; ks < 2; ks++) {
            int k = ks << 3;
            uint32_t af[2][4];
#pragma unroll
            for (int mi = 0; mi < 2; mi++) {
                int m0 = wm * 32 + mi * 16;
                af[mi][0] = As[cur][m0 + g][k + t];
                af[mi][1] = As[cur][m0 + g + 8][k + t];
                af[mi][2] = As[cur][m0 + g][k + t + 4];
                af[mi][3] = As[cur][m0 + g + 8][k + t + 4];
            }
            uint32_t bf[8][2];
#pragma unroll
            for (int ni = 0; ni < 8; ni++) {
                int n0 = wn * 64 + ni * 8;
                bf[ni][0] = Bs[cur][k + t][n0 + g];
                bf[ni][1] = Bs[cur][k + t + 4][n0 + g];
            }
#pragma unroll
            for (int mi = 0; mi < 2; mi++)
#pragma unroll
                for (int ni = 0; ni < 8; ni++) {
                    asm volatile(
                        "mma.sync.aligned.m16n8k8.row.col.f32.tf32.tf32.f32 "
                        "{%0,%1,%2,%3}, {%4,%5,%6,%7}, {%8,%9}, {%0,%1,%2,%3};"
                        : "+f"(c[mi][ni][0]), "+f"(c[mi][ni][1]),
                          "+f"(c[mi][ni][2]), "+f"(c[mi][ni][3])
                        : "r"(af[mi][0]), "r"(af[mi][1]), "r"(af[mi][2]), "r"(af[mi][3]),
                          "r"(bf[ni][0]), "r"(bf[ni][1]));
                }
        }
        __syncthreads();
    }

    // epilogue: bias + relu, guarded stores
#pragma unroll
    for (int mi = 0; mi < 2; mi++) {
        int r = row0 + wm * 32 + mi * 16 + g;
#pragma unroll
        for (int ni = 0; ni < 8; ni++) {
            int cn = col0 + wn * 64 + ni * 8 + (t << 1);
            float2 bb = *(const float2*)&bias[cn];
            if (r < M) {
                float2 o;
                o.x = fmaxf(c[mi][ni][0] + bb.x, 0.f);
                o.y = fmaxf(c[mi][ni][1] + bb.y, 0.f);
                *(float2*)&C[(size_t)r * N + cn] = o;
            }
            if (r + 8 < M) {
                float2 o;
                o.x = fmaxf(c[mi][ni][2] + bb.x, 0.f);
                o.y = fmaxf(c[mi][ni][3] + bb.y, 0.f);
                *(float2*)&C[(size_t)(r + 8) * N + cn] = o;
            }
        }
    }
}

// ---------------- small fp32 SIMT GEMM: 64x64 tile, 4x4 microtile (N=64) --------
// A = g_hidden, C = g_h0, no relu
__global__ void __launch_bounds__(256) k_gemm2(
    const float* __restrict__ B, const float* __restrict__ bias,
    int M, int N, int K)
{
    const float* A = (const float*)g_hidden;
    float* C = (float*)g_h0;

    const int BK = 16;
    __shared__ float As[BK][68];
    __shared__ float Bs[BK][68];

    int tid = threadIdx.x;
    int tx = tid & 15, ty = tid >> 4;
    int row0 = blockIdx.x * 64;
    int col0 = blockIdx.y * 64;

    int la_m = tid >> 2;
    int la_k = (tid & 3) << 2;
    int lb_k = tid >> 4;
    int lb_n = (tid & 15) << 2;

    const float* Aptr = A + (size_t)(row0 + la_m) * K + la_k;
    bool arow_ok = (row0 + la_m) < M;
    const float* Bptr = B + (size_t)lb_k * N + col0 + lb_n;

    float acc[4][4] = {};

    for (int k0 = 0; k0 < K; k0 += BK) {
        float4 av = make_float4(0.f, 0.f, 0.f, 0.f);
        if (arow_ok) av = *(const float4*)(Aptr + k0);
        As[la_k + 0][la_m] = av.x;
        As[la_k + 1][la_m] = av.y;
        As[la_k + 2][la_m] = av.z;
        As[la_k + 3][la_m] = av.w;
        *(float4*)&Bs[lb_k][lb_n] = *(const float4*)(Bptr + (size_t)k0 * N);
        __syncthreads();
#pragma unroll
        for (int k = 0; k < BK; k++) {
            float4 a = *(const float4*)&As[k][ty << 2];
            float4 b = *(const float4*)&Bs[k][tx << 2];
            acc[0][0] = fmaf(a.x, b.x, acc[0][0]); acc[0][1] = fmaf(a.x, b.y, acc[0][1]);
            acc[0][2] = fmaf(a.x, b.z, acc[0][2]); acc[0][3] = fmaf(a.x, b.w, acc[0][3]);
            acc[1][0] = fmaf(a.y, b.x, acc[1][0]); acc[1][1] = fmaf(a.y, b.y, acc[1][1]);
            acc[1][2] = fmaf(a.y, b.z, acc[1][2]); acc[1][3] = fmaf(a.y, b.w, acc[1][3]);
            acc[2][0] = fmaf(a.z, b.x, acc[2][0]); acc[2][1] = fmaf(a.z, b.y, acc[2][1]);
            acc[2][2] = fmaf(a.z, b.z, acc[2][2]); acc[2][3] = fmaf(a.z, b.w, acc[2][3]);
            acc[3][0] = fmaf(a.w, b.x, acc[3][0]); acc[3][1] = fmaf(a.w, b.y, acc[3][1]);
            acc[3][2] = fmaf(a.w, b.z, acc[3][2]); acc[3][3] = fmaf(a.w, b.w, acc[3][3]);
        }
        __syncthreads();
    }

    float4 bb = *(const float4*)&bias[col0 + (tx << 2)];
#pragma unroll
    for (int i = 0; i < 4; i++) {
        int r = row0 + (ty << 2) + i;
        if (r < M) {
            float4 o;
            o.x = acc[i][0] + bb.x;
            o.y = acc[i][1] + bb.y;
            o.z = acc[i][2] + bb.z;
            o.w = acc[i][3] + bb.w;
            *(float4*)&C[(size_t)r * N + col0 + (tx << 2)] = o;
        }
    }
}

// ---------------- propagation: hout = 0.9 * (P @ hin) + 0.1 * h0 ----------------
// one warp per dst node; lane l handles columns 2l, 2l+1
// Buffer ids: 0 = g_h0, 1 = g_hA, 2 = g_hB, 3 = external out (param)
__global__ void __launch_bounds__(256) k_prop(int src_id, int dst_id,
                                              float* __restrict__ ext_out)
{
    const float* hin = (src_id == 0) ? (const float*)g_h0
                     : (src_id == 1) ? (const float*)g_hA
                                     : (const float*)g_hB;
    float* hout = (dst_id == 1) ? (float*)g_hA
                : (dst_id == 2) ? (float*)g_hB
                                : ext_out;

    int node = (blockIdx.x * blockDim.x + threadIdx.x) >> 5;
    int lane = threadIdx.x & 31;
    if (node >= NN) return;
    int beg = g_rowptr[node];
    int end = g_rowptr[node + 1];
    int c0 = lane << 1;
    float ax = 0.f, ay = 0.f;
    for (int base = beg; base < end; base += 32) {
        int nb = end - base; if (nb > 32) nb = 32;
        int2 ed = make_int2(0, 0);
        if (lane < nb) ed = g_edge[base + lane];
#pragma unroll 4
        for (int j = 0; j < nb; j++) {
            int   s  = __shfl_sync(0xffffffffu, ed.x, j);
            float ww = __int_as_float(__shfl_sync(0xffffffffu, ed.y, j));
            float2 hv = *(const float2*)(hin + (size_t)s * OUTC + c0);
            ax = fmaf(ww, hv.x, ax);
            ay = fmaf(ww, hv.y, ay);
        }
    }
    // self loop: norm = dinv[node]^2
    float dv = g_dinv[node];
    float sw = dv * dv;
    float2 hs = *(const float2*)(hin + (size_t)node * OUTC + c0);
    ax = fmaf(sw, hs.x, ax);
    ay = fmaf(sw, hs.y, ay);
    float2 h0v = *(const float2*)(g_h0 + (size_t)node * OUTC + c0);
    float2 o;
    o.x = 0.9f * ax + 0.1f * h0v.x;
    o.y = 0.9f * ay + 0.1f * h0v.y;
    *(float2*)(hout + (size_t)node * OUTC + c0) = o;
}

// ---------------- launch ----------------
extern "C" void kernel_launch(void* const* d_in, const int* in_sizes, int n_in,
                              void* d_out, int out_size)
{
    const float* x  = (const float*)d_in[0];
    const int*   ei = (const int*)d_in[1];     // int32 (JAX x64 disabled)
    const float* W1 = (const float*)d_in[2];
    const float* b1 = (const float*)d_in[3];
    const float* W2 = (const float*)d_in[4];
    const float* b2 = (const float*)d_in[5];
    float* out = (float*)d_out;

    static cudaStream_t s2 = nullptr;
    static cudaEvent_t evFork = nullptr, evJoin = nullptr;
    if (s2 == nullptr) {
        cudaStreamCreateWithFlags(&s2, cudaStreamNonBlocking);
        cudaEventCreateWithFlags(&evFork, cudaEventDisableTiming);
        cudaEventCreateWithFlags(&evJoin, cudaEventDisableTiming);
    }

    // fork: graph preprocessing -> CSR by dst, on side stream
    cudaEventRecord(evFork, 0);
    cudaStreamWaitEvent(s2, evFork, 0);
    k_zero_cnt<<<(NN + 255) / 256, 256, 0, s2>>>();
    k_count<<<(NE + 255) / 256, 256, 0, s2>>>(ei);
    k_dinv<<<(NN + 255) / 256, 256, 0, s2>>>();
    k_scan1<<<NBLK_SCAN, 1024, 0, s2>>>();
    k_scan2<<<1, 32, 0, s2>>>();
    k_scan3<<<(NN + 255) / 256, 256, 0, s2>>>();
    k_fill<<<(NE + 255) / 256, 256, 0, s2>>>(ei);
    cudaEventRecord(evJoin, s2);

    // MLP encoder on main stream (independent of CSR build)
    dim3 g1((NN + 127) / 128, HID / 128);
    k_gemm1_tf32<<<g1, 256>>>(x, W1, b1, NN, HID, INC);
    dim3 g2((NN + 63) / 64, OUTC / 64);
    k_gemm2<<<g2, 256>>>(W2, b2, NN, OUTC, HID);

    // join: propagation needs both the CSR and h0
    cudaStreamWaitEvent(0, evJoin, 0);

    // 10 propagation iterations (ping-pong; last writes d_out)
    int pgrid = (NN * 32 + 255) / 256;
    k_prop<<<pgrid, 256>>>(0, 1, out);
    k_prop<<<pgrid, 256>>>(1, 2, out);
    k_prop<<<pgrid, 256>>>(2, 1, out);
    k_prop<<<pgrid, 256>>>(1, 2, out);
    k_prop<<<pgrid, 256>>>(2, 1, out);
    k_prop<<<pgrid, 256>>>(1, 2, out);
    k_prop<<<pgrid, 256>>>(2, 1, out);
    k_prop<<<pgrid, 256>>>(1, 2, out);
    k_prop<<<pgrid, 256>>>(2, 1, out);
    k_prop<<<pgrid, 256>>>(1, 3, out);
    (void)in_sizes; (void)n_in; (void)out_size;
}

// round 9
// speedup vs baseline: 1.5233x; 1.1551x over previous
#include <cuda_runtime.h>
#include <cuda_fp16.h>
#include <cstdint>

// Problem constants (fixed by the dataset)
#define NN        100000
#define NE        3200000
#define INC       512
#define HID       256
#define OUTC      64
#define NBLK_SCAN 98      // ceil(NN / 1024)

// ---------------- scratch (static __device__ — no allocations) ----------------
__device__ float   g_hidden[(size_t)NN * HID];     // 102.4 MB
__device__ float   g_h0[(size_t)NN * OUTC];        // 25.6 MB (fp32 residual)
__device__ __half2 g_h016[(size_t)NN * (OUTC/2)];  // 12.8 MB (fp16 gather copy)
__device__ __half2 g_hA16[(size_t)NN * (OUTC/2)];
__device__ __half2 g_hB16[(size_t)NN * (OUTC/2)];
__device__ int     g_cnt[NN];
__device__ int     g_rowptr[NN + 1];
__device__ int     g_fillpos[NN];
__device__ float   g_dinv[NN];
__device__ int2    g_edge[NE];                     // (src, w_bits) 25.6 MB
__device__ int     g_bsums[NBLK_SCAN];

// ---------------- graph preprocessing ----------------
__global__ void k_zero_cnt() {
    int i = blockIdx.x * blockDim.x + threadIdx.x;
    if (i < NN) g_cnt[i] = 0;
}

// ei is int32 (JAX default x64-disabled downgrades int64 -> int32)
__global__ void k_count(const int* __restrict__ ei) {
    int e = blockIdx.x * blockDim.x + threadIdx.x;
    if (e < NE) {
        int d = ei[NE + e];
        if (d >= 0 && d < NN) atomicAdd(&g_cnt[d], 1);
    }
}

__global__ void k_dinv() {
    int i = blockIdx.x * blockDim.x + threadIdx.x;
    if (i < NN) g_dinv[i] = rsqrtf((float)(g_cnt[i] + 1)); // +1 self loop
}

__global__ void k_scan1() {
    __shared__ int s[1024];
    int tid = threadIdx.x;
    int i = blockIdx.x * 1024 + tid;
    int v = (i < NN) ? g_cnt[i] : 0;
    s[tid] = v;
    __syncthreads();
    for (int off = 1; off < 1024; off <<= 1) {
        int t = (tid >= off) ? s[tid - off] : 0;
        __syncthreads();
        s[tid] += t;
        __syncthreads();
    }
    if (i < NN) g_rowptr[i] = s[tid];
    if (tid == 1023) g_bsums[blockIdx.x] = s[1023];
}

__global__ void k_scan2() {
    if (threadIdx.x == 0) {
        int run = 0;
        for (int b = 0; b < NBLK_SCAN; b++) { int t = g_bsums[b]; g_bsums[b] = run; run += t; }
    }
}

__global__ void k_scan3() {
    int i = blockIdx.x * blockDim.x + threadIdx.x;
    if (i < NN) {
        int ex = g_rowptr[i] - g_cnt[i] + g_bsums[i >> 10]; // global exclusive
        g_rowptr[i]  = ex;
        g_fillpos[i] = ex;
    }
    if (i == 0) g_rowptr[NN] = NE;
}

__global__ void k_fill(const int* __restrict__ ei) {
    int e = blockIdx.x * blockDim.x + threadIdx.x;
    if (e < NE) {
        int s = ei[e];
        int d = ei[NE + e];
        if (s >= 0 && s < NN && d >= 0 && d < NN) {
            int p = atomicAdd(&g_fillpos[d], 1);
            float w = g_dinv[s] * g_dinv[d];
            g_edge[p] = make_int2(s, __float_as_int(w));
        }
    }
}

// ---------------- tf32 tensor-core GEMM1: C = relu(A @ B + bias) --------------
// 128x128 tile, BK=16, 8 warps (4m x 2n), warp tile 32x64, mma.m16n8k8 tf32
__device__ __forceinline__ uint32_t f2tf(float f) {
    uint32_t u;
    asm("cvt.rna.tf32.f32 %0, %1;" : "=r"(u) : "f"(f));
    return u;
}

__global__ void __launch_bounds__(256) k_gemm1_tf32(
    const float* __restrict__ A, const float* __restrict__ B,
    const float* __restrict__ bias, int M, int N, int K)
{
    float* C = (float*)g_hidden;
    __shared__ uint32_t As[2][128][20];   // [buf][m][k]
    __shared__ uint32_t Bs[2][16][136];   // [buf][k][n]

    int tid = threadIdx.x;
    int lane = tid & 31, wid = tid >> 5;
    int wm = wid & 3, wn = wid >> 2;       // warp tile: rows wm*32, cols wn*64
    int g = lane >> 2, t = lane & 3;
    int row0 = blockIdx.x * 128, col0 = blockIdx.y * 128;

    int ar0 = tid >> 2;
    int ac  = (tid & 3) << 2;
    int br0 = tid >> 5;
    int bc  = (tid & 31) << 2;

    const float* Ap0 = A + (size_t)(row0 + ar0) * K + ac;
    const float* Ap1 = A + (size_t)(row0 + ar0 + 64) * K + ac;
    bool aok0 = (row0 + ar0) < M;
    bool aok1 = (row0 + ar0 + 64) < M;
    const float* Bp0 = B + (size_t)br0 * N + col0 + bc;
    const float* Bp1 = B + (size_t)(br0 + 8) * N + col0 + bc;

    float c[2][8][4] = {};

    const float4 fz = make_float4(0.f, 0.f, 0.f, 0.f);
    float4 av0 = aok0 ? *(const float4*)Ap0 : fz;
    float4 av1 = aok1 ? *(const float4*)Ap1 : fz;
    float4 bv0 = *(const float4*)Bp0;
    float4 bv1 = *(const float4*)Bp1;

    int nk = K >> 4;
    for (int kt = 0; kt < nk; kt++) {
        int cur = kt & 1;
        *(uint4*)&As[cur][ar0][ac]      = make_uint4(f2tf(av0.x), f2tf(av0.y), f2tf(av0.z), f2tf(av0.w));
        *(uint4*)&As[cur][ar0 + 64][ac] = make_uint4(f2tf(av1.x), f2tf(av1.y), f2tf(av1.z), f2tf(av1.w));
        *(uint4*)&Bs[cur][br0][bc]      = make_uint4(f2tf(bv0.x), f2tf(bv0.y), f2tf(bv0.z), f2tf(bv0.w));
        *(uint4*)&Bs[cur][br0 + 8][bc]  = make_uint4(f2tf(bv1.x), f2tf(bv1.y), f2tf(bv1.z), f2tf(bv1.w));
        __syncthreads();

        if (kt + 1 < nk) {
            int ko = (kt + 1) << 4;
            av0 = aok0 ? *(const float4*)(Ap0 + ko) : fz;
            av1 = aok1 ? *(const float4*)(Ap1 + ko) : fz;
            bv0 = *(const float4*)(Bp0 + (size_t)ko * N);
            bv1 = *(const float4*)(Bp1 + (size_t)ko * N);
        }

#pragma unroll
        for (int ks = 0; ks < 2; ks++) {
            int k = ks << 3;
            uint32_t af[2][4];
#pragma unroll
            for (int mi = 0; mi < 2; mi++) {
                int m0 = wm * 32 + mi * 16;
                af[mi][0] = As[cur][m0 + g][k + t];
                af[mi][1] = As[cur][m0 + g + 8][k + t];
                af[mi][2] = As[cur][m0 + g][k + t + 4];
                af[mi][3] = As[cur][m0 + g + 8][k + t + 4];
            }
            uint32_t bf[8][2];
#pragma unroll
            for (int ni = 0; ni < 8; ni++) {
                int n0 = wn * 64 + ni * 8;
                bf[ni][0] = Bs[cur][k + t][n0 + g];
                bf[ni][1] = Bs[cur][k + t + 4][n0 + g];
            }
#pragma unroll
            for (int mi = 0; mi < 2; mi++)
#pragma unroll
                for (int ni = 0; ni < 8; ni++) {
                    asm volatile(
                        "mma.sync.aligned.m16n8k8.row.col.f32.tf32.tf32.f32 "
                        "{%0,%1,%2,%3}, {%4,%5,%6,%7}, {%8,%9}, {%0,%1,%2,%3};"
                        : "+f"(c[mi][ni][0]), "+f"(c[mi][ni][1]),
                          "+f"(c[mi][ni][2]), "+f"(c[mi][ni][3])
                        : "r"(af[mi][0]), "r"(af[mi][1]), "r"(af[mi][2]), "r"(af[mi][3]),
                          "r"(bf[ni][0]), "r"(bf[ni][1]));
                }
        }
        __syncthreads();
    }

#pragma unroll
    for (int mi = 0; mi < 2; mi++) {
        int r = row0 + wm * 32 + mi * 16 + g;
#pragma unroll
        for (int ni = 0; ni < 8; ni++) {
            int cn = col0 + wn * 64 + ni * 8 + (t << 1);
            float2 bb = *(const float2*)&bias[cn];
            if (r < M) {
                float2 o;
                o.x = fmaxf(c[mi][ni][0] + bb.x, 0.f);
                o.y = fmaxf(c[mi][ni][1] + bb.y, 0.f);
                *(float2*)&C[(size_t)r * N + cn] = o;
            }
            if (r + 8 < M) {
                float2 o;
                o.x = fmaxf(c[mi][ni][2] + bb.x, 0.f);
                o.y = fmaxf(c[mi][ni][3] + bb.y, 0.f);
                *(float2*)&C[(size_t)(r + 8) * N + cn] = o;
            }
        }
    }
}

// ---------------- small fp32 SIMT GEMM2: 64x64 tile, 4x4 microtile (N=64) --------
// A = g_hidden, C = g_h0 (fp32) + g_h016 (fp16), no relu
__global__ void __launch_bounds__(256) k_gemm2(
    const float* __restrict__ B, const float* __restrict__ bias,
    int M, int N, int K)
{
    const float* A = (const float*)g_hidden;
    float* C = (float*)g_h0;

    const int BK = 16;
    __shared__ float As[BK][68];
    __shared__ float Bs[BK][68];

    int tid = threadIdx.x;
    int tx = tid & 15, ty = tid >> 4;
    int row0 = blockIdx.x * 64;
    int col0 = blockIdx.y * 64;

    int la_m = tid >> 2;
    int la_k = (tid & 3) << 2;
    int lb_k = tid >> 4;
    int lb_n = (tid & 15) << 2;

    const float* Aptr = A + (size_t)(row0 + la_m) * K + la_k;
    bool arow_ok = (row0 + la_m) < M;
    const float* Bptr = B + (size_t)lb_k * N + col0 + lb_n;

    float acc[4][4] = {};

    for (int k0 = 0; k0 < K; k0 += BK) {
        float4 av = make_float4(0.f, 0.f, 0.f, 0.f);
        if (arow_ok) av = *(const float4*)(Aptr + k0);
        As[la_k + 0][la_m] = av.x;
        As[la_k + 1][la_m] = av.y;
        As[la_k + 2][la_m] = av.z;
        As[la_k + 3][la_m] = av.w;
        *(float4*)&Bs[lb_k][lb_n] = *(const float4*)(Bptr + (size_t)k0 * N);
        __syncthreads();
#pragma unroll
        for (int k = 0; k < BK; k++) {
            float4 a = *(const float4*)&As[k][ty << 2];
            float4 b = *(const float4*)&Bs[k][tx << 2];
            acc[0][0] = fmaf(a.x, b.x, acc[0][0]); acc[0][1] = fmaf(a.x, b.y, acc[0][1]);
            acc[0][2] = fmaf(a.x, b.z, acc[0][2]); acc[0][3] = fmaf(a.x, b.w, acc[0][3]);
            acc[1][0] = fmaf(a.y, b.x, acc[1][0]); acc[1][1] = fmaf(a.y, b.y, acc[1][1]);
            acc[1][2] = fmaf(a.y, b.z, acc[1][2]); acc[1][3] = fmaf(a.y, b.w, acc[1][3]);
            acc[2][0] = fmaf(a.z, b.x, acc[2][0]); acc[2][1] = fmaf(a.z, b.y, acc[2][1]);
            acc[2][2] = fmaf(a.z, b.z, acc[2][2]); acc[2][3] = fmaf(a.z, b.w, acc[2][3]);
            acc[3][0] = fmaf(a.w, b.x, acc[3][0]); acc[3][1] = fmaf(a.w, b.y, acc[3][1]);
            acc[3][2] = fmaf(a.w, b.z, acc[3][2]); acc[3][3] = fmaf(a.w, b.w, acc[3][3]);
        }
        __syncthreads();
    }

    float4 bb = *(const float4*)&bias[col0 + (tx << 2)];
#pragma unroll
    for (int i = 0; i < 4; i++) {
        int r = row0 + (ty << 2) + i;
        if (r < M) {
            float4 o;
            o.x = acc[i][0] + bb.x;
            o.y = acc[i][1] + bb.y;
            o.z = acc[i][2] + bb.z;
            o.w = acc[i][3] + bb.w;
            *(float4*)&C[(size_t)r * N + col0 + (tx << 2)] = o;
            // fp16 copy for the propagation gather path
            __half2 h01 = __floats2half2_rn(o.x, o.y);
            __half2 h23 = __floats2half2_rn(o.z, o.w);
            int hc = (col0 + (tx << 2)) >> 1;
            g_h016[(size_t)r * (OUTC / 2) + hc]     = h01;
            g_h016[(size_t)r * (OUTC / 2) + hc + 1] = h23;
        }
    }
}

// ---------------- propagation: hout = 0.9 * (P @ hin) + 0.1 * h0 ----------------
// one warp per dst node; lane l handles columns 2l, 2l+1 (one half2)
// Buffer ids: 0 = g_h016, 1 = g_hA16, 2 = g_hB16; dst 3 = fp32 ext_out (final)
__global__ void __launch_bounds__(256) k_prop(int src_id, int dst_id,
                                              float* __restrict__ ext_out)
{
    const __half2* hin = (src_id == 0) ? (const __half2*)g_h016
                       : (src_id == 1) ? (const __half2*)g_hA16
                                       : (const __half2*)g_hB16;
    __half2* hout16 = (dst_id == 1) ? (__half2*)g_hA16
                    : (dst_id == 2) ? (__half2*)g_hB16
                                    : nullptr;

    int node = (blockIdx.x * blockDim.x + threadIdx.x) >> 5;
    int lane = threadIdx.x & 31;
    if (node >= NN) return;
    int beg = g_rowptr[node];
    int end = g_rowptr[node + 1];
    float ax = 0.f, ay = 0.f;
    for (int base = beg; base < end; base += 32) {
        int nb = end - base; if (nb > 32) nb = 32;
        int2 ed = make_int2(0, 0);
        if (lane < nb) ed = g_edge[base + lane];
#pragma unroll 4
        for (int j = 0; j < nb; j++) {
            int   s  = __shfl_sync(0xffffffffu, ed.x, j);
            float ww = __int_as_float(__shfl_sync(0xffffffffu, ed.y, j));
            float2 hv = __half22float2(hin[(size_t)s * (OUTC / 2) + lane]);
            ax = fmaf(ww, hv.x, ax);
            ay = fmaf(ww, hv.y, ay);
        }
    }
    // self loop: norm = dinv[node]^2
    float dv = g_dinv[node];
    float sw = dv * dv;
    float2 hs = __half22float2(hin[(size_t)node * (OUTC / 2) + lane]);
    ax = fmaf(sw, hs.x, ax);
    ay = fmaf(sw, hs.y, ay);
    // residual from fp32 h0
    float2 h0v = *(const float2*)(g_h0 + (size_t)node * OUTC + (lane << 1));
    float ox = 0.9f * ax + 0.1f * h0v.x;
    float oy = 0.9f * ay + 0.1f * h0v.y;
    if (hout16) {
        hout16[(size_t)node * (OUTC / 2) + lane] = __floats2half2_rn(ox, oy);
    } else {
        *(float2*)(ext_out + (size_t)node * OUTC + (lane << 1)) = make_float2(ox, oy);
    }
}

// ---------------- launch ----------------
extern "C" void kernel_launch(void* const* d_in, const int* in_sizes, int n_in,
                              void* d_out, int out_size)
{
    const float* x  = (const float*)d_in[0];
    const int*   ei = (const int*)d_in[1];     // int32 (JAX x64 disabled)
    const float* W1 = (const float*)d_in[2];
    const float* b1 = (const float*)d_in[3];
    const float* W2 = (const float*)d_in[4];
    const float* b2 = (const float*)d_in[5];
    float* out = (float*)d_out;

    static cudaStream_t s2 = nullptr;
    static cudaEvent_t evFork = nullptr, evJoin = nullptr;
    if (s2 == nullptr) {
        cudaStreamCreateWithFlags(&s2, cudaStreamNonBlocking);
        cudaEventCreateWithFlags(&evFork, cudaEventDisableTiming);
        cudaEventCreateWithFlags(&evJoin, cudaEventDisableTiming);
    }

    // fork: graph preprocessing -> CSR by dst, on side stream
    cudaEventRecord(evFork, 0);
    cudaStreamWaitEvent(s2, evFork, 0);
    k_zero_cnt<<<(NN + 255) / 256, 256, 0, s2>>>();
    k_count<<<(NE + 255) / 256, 256, 0, s2>>>(ei);
    k_dinv<<<(NN + 255) / 256, 256, 0, s2>>>();
    k_scan1<<<NBLK_SCAN, 1024, 0, s2>>>();
    k_scan2<<<1, 32, 0, s2>>>();
    k_scan3<<<(NN + 255) / 256, 256, 0, s2>>>();
    k_fill<<<(NE + 255) / 256, 256, 0, s2>>>(ei);
    cudaEventRecord(evJoin, s2);

    // MLP encoder on main stream (independent of CSR build)
    dim3 g1((NN + 127) / 128, HID / 128);
    k_gemm1_tf32<<<g1, 256>>>(x, W1, b1, NN, HID, INC);
    dim3 g2((NN + 63) / 64, OUTC / 64);
    k_gemm2<<<g2, 256>>>(W2, b2, NN, OUTC, HID);

    // join: propagation needs both the CSR and h0
    cudaStreamWaitEvent(0, evJoin, 0);

    // 10 propagation iterations (ping-pong fp16; last writes fp32 d_out)
    int pgrid = (NN * 32 + 255) / 256;
    k_prop<<<pgrid, 256>>>(0, 1, out);
    k_prop<<<pgrid, 256>>>(1, 2, out);
    k_prop<<<pgrid, 256>>>(2, 1, out);
    k_prop<<<pgrid, 256>>>(1, 2, out);
    k_prop<<<pgrid, 256>>>(2, 1, out);
    k_prop<<<pgrid, 256>>>(1, 2, out);
    k_prop<<<pgrid, 256>>>(2, 1, out);
    k_prop<<<pgrid, 256>>>(1, 2, out);
    k_prop<<<pgrid, 256>>>(2, 1, out);
    k_prop<<<pgrid, 256>>>(1, 3, out);
    (void)in_sizes; (void)n_in; (void)out_size;
}

// round 12
// speedup vs baseline: 1.7524x; 1.1504x over previous
#include <cuda_runtime.h>
#include <cuda_fp16.h>
#include <cstdint>

// Problem constants (fixed by the dataset)
#define NN        100000
#define NE        3200000
#define INC       512
#define HID       256
#define OUTC      64
#define NBLK_SCAN 98      // ceil(NN / 1024)

// ---------------- scratch (static __device__ — no allocations) ----------------
__device__ float   g_hidden[(size_t)NN * HID];     // 102.4 MB
__device__ float   g_h0[(size_t)NN * OUTC];        // 25.6 MB (fp32 residual)
__device__ __half2 g_h016[(size_t)NN * (OUTC/2)];  // prescaled fp16 (dinv*h)
__device__ __half2 g_hA16[(size_t)NN * (OUTC/2)];
__device__ __half2 g_hB16[(size_t)NN * (OUTC/2)];
__device__ int     g_cnt[NN];
__device__ int     g_rowptr[NN + 1];
__device__ int     g_fillpos[NN];
__device__ float   g_dinv[NN];
__device__ int     g_esrc[NE];                     // src only, 12.8 MB
__device__ int     g_bsums[NBLK_SCAN];

// ---------------- graph preprocessing ----------------
__global__ void k_zero_cnt() {
    int i = blockIdx.x * blockDim.x + threadIdx.x;
    if (i < NN) g_cnt[i] = 0;
}

// ei is int32 (JAX default x64-disabled downgrades int64 -> int32)
__global__ void k_count(const int* __restrict__ ei) {
    int e = blockIdx.x * blockDim.x + threadIdx.x;
    if (e < NE) {
        int d = ei[NE + e];
        if (d >= 0 && d < NN) atomicAdd(&g_cnt[d], 1);
    }
}

__global__ void k_dinv() {
    int i = blockIdx.x * blockDim.x + threadIdx.x;
    if (i < NN) g_dinv[i] = rsqrtf((float)(g_cnt[i] + 1)); // +1 self loop
}

__global__ void k_scan1() {
    __shared__ int s[1024];
    int tid = threadIdx.x;
    int i = blockIdx.x * 1024 + tid;
    int v = (i < NN) ? g_cnt[i] : 0;
    s[tid] = v;
    __syncthreads();
    for (int off = 1; off < 1024; off <<= 1) {
        int t = (tid >= off) ? s[tid - off] : 0;
        __syncthreads();
        s[tid] += t;
        __syncthreads();
    }
    if (i < NN) g_rowptr[i] = s[tid];
    if (tid == 1023) g_bsums[blockIdx.x] = s[1023];
}

__global__ void k_scan2() {
    if (threadIdx.x == 0) {
        int run = 0;
        for (int b = 0; b < NBLK_SCAN; b++) { int t = g_bsums[b]; g_bsums[b] = run; run += t; }
    }
}

__global__ void k_scan3() {
    int i = blockIdx.x * blockDim.x + threadIdx.x;
    if (i < NN) {
        int ex = g_rowptr[i] - g_cnt[i] + g_bsums[i >> 10]; // global exclusive
        g_rowptr[i]  = ex;
        g_fillpos[i] = ex;
    }
    if (i == 0) g_rowptr[NN] = NE;
}

__global__ void k_fill(const int* __restrict__ ei) {
    int e = blockIdx.x * blockDim.x + threadIdx.x;
    if (e < NE) {
        int s = ei[e];
        int d = ei[NE + e];
        if (s >= 0 && s < NN && d >= 0 && d < NN) {
            int p = atomicAdd(&g_fillpos[d], 1);
            g_esrc[p] = s;
        }
    }
}

// prescale h0 -> fp16 gather buffer: hs16 = dinv * h0
__global__ void k_prescale() {
    int idx = blockIdx.x * blockDim.x + threadIdx.x;   // over NN*32 half2
    if (idx < NN * (OUTC / 2)) {
        int node = idx >> 5;
        float dv = g_dinv[node];
        float2 f = *(const float2*)(g_h0 + ((size_t)idx << 1));
        g_h016[idx] = __floats2half2_rn(dv * f.x, dv * f.y);
    }
}

// ---------------- tf32 helpers ----------------
__device__ __forceinline__ uint32_t f2tf(float f) {
    uint32_t u;
    asm("cvt.rna.tf32.f32 %0, %1;" : "=r"(u) : "f"(f));
    return u;
}

// ---------------- tf32 tensor-core GEMM1: C = relu(A @ B + bias) --------------
// 128x128 tile, BK=16, 8 warps (4m x 2n), warp tile 32x64, mma.m16n8k8 tf32
__global__ void __launch_bounds__(256) k_gemm1_tf32(
    const float* __restrict__ A, const float* __restrict__ B,
    const float* __restrict__ bias, int M, int N, int K)
{
    float* C = (float*)g_hidden;
    __shared__ uint32_t As[2][128][20];
    __shared__ uint32_t Bs[2][16][136];

    int tid = threadIdx.x;
    int lane = tid & 31, wid = tid >> 5;
    int wm = wid & 3, wn = wid >> 2;
    int g = lane >> 2, t = lane & 3;
    int row0 = blockIdx.x * 128, col0 = blockIdx.y * 128;

    int ar0 = tid >> 2;
    int ac  = (tid & 3) << 2;
    int br0 = tid >> 5;
    int bc  = (tid & 31) << 2;

    const float* Ap0 = A + (size_t)(row0 + ar0) * K + ac;
    const float* Ap1 = A + (size_t)(row0 + ar0 + 64) * K + ac;
    bool aok0 = (row0 + ar0) < M;
    bool aok1 = (row0 + ar0 + 64) < M;
    const float* Bp0 = B + (size_t)br0 * N + col0 + bc;
    const float* Bp1 = B + (size_t)(br0 + 8) * N + col0 + bc;

    float c[2][8][4] = {};

    const float4 fz = make_float4(0.f, 0.f, 0.f, 0.f);
    float4 av0 = aok0 ? *(const float4*)Ap0 : fz;
    float4 av1 = aok1 ? *(const float4*)Ap1 : fz;
    float4 bv0 = *(const float4*)Bp0;
    float4 bv1 = *(const float4*)Bp1;

    int nk = K >> 4;
    for (int kt = 0; kt < nk; kt++) {
        int cur = kt & 1;
        *(uint4*)&As[cur][ar0][ac]      = make_uint4(f2tf(av0.x), f2tf(av0.y), f2tf(av0.z), f2tf(av0.w));
        *(uint4*)&As[cur][ar0 + 64][ac] = make_uint4(f2tf(av1.x), f2tf(av1.y), f2tf(av1.z), f2tf(av1.w));
        *(uint4*)&Bs[cur][br0][bc]      = make_uint4(f2tf(bv0.x), f2tf(bv0.y), f2tf(bv0.z), f2tf(bv0.w));
        *(uint4*)&Bs[cur][br0 + 8][bc]  = make_uint4(f2tf(bv1.x), f2tf(bv1.y), f2tf(bv1.z), f2tf(bv1.w));
        __syncthreads();

        if (kt + 1 < nk) {
            int ko = (kt + 1) << 4;
            av0 = aok0 ? *(const float4*)(Ap0 + ko) : fz;
            av1 = aok1 ? *(const float4*)(Ap1 + ko) : fz;
            bv0 = *(const float4*)(Bp0 + (size_t)ko * N);
            bv1 = *(const float4*)(Bp1 + (size_t)ko * N);
        }

#pragma unroll
        for (int ks = 0; ks < 2; ks++) {
            int k = ks << 3;
            uint32_t af[2][4];
#pragma unroll
            for (int mi = 0; mi < 2; mi++) {
                int m0 = wm * 32 + mi * 16;
                af[mi][0] = As[cur][m0 + g][k + t];
                af[mi][1] = As[cur][m0 + g + 8][k + t];
                af[mi][2] = As[cur][m0 + g][k + t + 4];
                af[mi][3] = As[cur][m0 + g + 8][k + t + 4];
            }
            uint32_t bf[8][2];
#pragma unroll
            for (int ni = 0; ni < 8; ni++) {
                int n0 = wn * 64 + ni * 8;
                bf[ni][0] = Bs[cur][k + t][n0 + g];
                bf[ni][1] = Bs[cur][k + t + 4][n0 + g];
            }
#pragma unroll
            for (int mi = 0; mi < 2; mi++)
#pragma unroll
                for (int ni = 0; ni < 8; ni++) {
                    asm volatile(
                        "mma.sync.aligned.m16n8k8.row.col.f32.tf32.tf32.f32 "
                        "{%0,%1,%2,%3}, {%4,%5,%6,%7}, {%8,%9}, {%0,%1,%2,%3};"
                        : "+f"(c[mi][ni][0]), "+f"(c[mi][ni][1]),
                          "+f"(c[mi][ni][2]), "+f"(c[mi][ni][3])
                        : "r"(af[mi][0]), "r"(af[mi][1]), "r"(af[mi][2]), "r"(af[mi][3]),
                          "r"(bf[ni][0]), "r"(bf[ni][1]));
                }
        }
        __syncthreads();
    }

#pragma unroll
    for (int mi = 0; mi < 2; mi++) {
        int r = row0 + wm * 32 + mi * 16 + g;
#pragma unroll
        for (int ni = 0; ni < 8; ni++) {
            int cn = col0 + wn * 64 + ni * 8 + (t << 1);
            float2 bb = *(const float2*)&bias[cn];
            if (r < M) {
                float2 o;
                o.x = fmaxf(c[mi][ni][0] + bb.x, 0.f);
                o.y = fmaxf(c[mi][ni][1] + bb.y, 0.f);
                *(float2*)&C[(size_t)r * N + cn] = o;
            }
            if (r + 8 < M) {
                float2 o;
                o.x = fmaxf(c[mi][ni][2] + bb.x, 0.f);
                o.y = fmaxf(c[mi][ni][3] + bb.y, 0.f);
                *(float2*)&C[(size_t)(r + 8) * N + cn] = o;
            }
        }
    }
}

// ---------------- tf32 tensor-core GEMM2: g_h0 = g_hidden @ W2 + b2 ------------
// 128x64 tile, BK=16, 8 warps (4m x 2n), warp tile 32x32
__global__ void __launch_bounds__(256) k_gemm2_tf32(
    const float* __restrict__ B, const float* __restrict__ bias,
    int M, int N, int K)
{
    const float* A = (const float*)g_hidden;
    float* C = (float*)g_h0;
    __shared__ uint32_t As[2][128][20];
    __shared__ uint32_t Bs[2][16][72];

    int tid = threadIdx.x;
    int lane = tid & 31, wid = tid >> 5;
    int wm = wid & 3, wn = wid >> 2;       // warp tile rows wm*32, cols wn*32
    int g = lane >> 2, t = lane & 3;
    int row0 = blockIdx.x * 128;

    int ar0 = tid >> 2;
    int ac  = (tid & 3) << 2;
    int br0 = tid >> 4;            // 0..15
    int bc  = (tid & 15) << 2;     // 0..60

    const float* Ap0 = A + (size_t)(row0 + ar0) * K + ac;
    const float* Ap1 = A + (size_t)(row0 + ar0 + 64) * K + ac;
    bool aok0 = (row0 + ar0) < M;
    bool aok1 = (row0 + ar0 + 64) < M;
    const float* Bp = B + (size_t)br0 * N + bc;

    float c[2][4][4] = {};

    const float4 fz = make_float4(0.f, 0.f, 0.f, 0.f);
    float4 av0 = aok0 ? *(const float4*)Ap0 : fz;
    float4 av1 = aok1 ? *(const float4*)Ap1 : fz;
    float4 bv = *(const float4*)Bp;

    int nk = K >> 4;   // 16
    for (int kt = 0; kt < nk; kt++) {
        int cur = kt & 1;
        *(uint4*)&As[cur][ar0][ac]      = make_uint4(f2tf(av0.x), f2tf(av0.y), f2tf(av0.z), f2tf(av0.w));
        *(uint4*)&As[cur][ar0 + 64][ac] = make_uint4(f2tf(av1.x), f2tf(av1.y), f2tf(av1.z), f2tf(av1.w));
        *(uint4*)&Bs[cur][br0][bc]      = make_uint4(f2tf(bv.x), f2tf(bv.y), f2tf(bv.z), f2tf(bv.w));
        __syncthreads();

        if (kt + 1 < nk) {
            int ko = (kt + 1) << 4;
            av0 = aok0 ? *(const float4*)(Ap0 + ko) : fz;
            av1 = aok1 ? *(const float4*)(Ap1 + ko) : fz;
            bv = *(const float4*)(Bp + (size_t)ko * N);
        }

#pragma unroll
        for (int ks = 0; ks < 2; ks++) {
            int k = ks << 3;
            uint32_t af[2][4];
#pragma unroll
            for (int mi = 0; mi < 2; mi++) {
                int m0 = wm * 32 + mi * 16;
                af[mi][0] = As[cur][m0 + g][k + t];
                af[mi][1] = As[cur][m0 + g + 8][k + t];
                af[mi][2] = As[cur][m0 + g][k + t + 4];
                af[mi][3] = As[cur][m0 + g + 8][k + t + 4];
            }
            uint32_t bf[4][2];
#pragma unroll
            for (int ni = 0; ni < 4; ni++) {
                int n0 = wn * 32 + ni * 8;
                bf[ni][0] = Bs[cur][k + t][n0 + g];
                bf[ni][1] = Bs[cur][k + t + 4][n0 + g];
            }
#pragma unroll
            for (int mi = 0; mi < 2; mi++)
#pragma unroll
                for (int ni = 0; ni < 4; ni++) {
                    asm volatile(
                        "mma.sync.aligned.m16n8k8.row.col.f32.tf32.tf32.f32 "
                        "{%0,%1,%2,%3}, {%4,%5,%6,%7}, {%8,%9}, {%0,%1,%2,%3};"
                        : "+f"(c[mi][ni][0]), "+f"(c[mi][ni][1]),
                          "+f"(c[mi][ni][2]), "+f"(c[mi][ni][3])
                        : "r"(af[mi][0]), "r"(af[mi][1]), "r"(af[mi][2]), "r"(af[mi][3]),
                          "r"(bf[ni][0]), "r"(bf[ni][1]));
                }
        }
        __syncthreads();
    }

#pragma unroll
    for (int mi = 0; mi < 2; mi++) {
        int r = row0 + wm * 32 + mi * 16 + g;
#pragma unroll
        for (int ni = 0; ni < 4; ni++) {
            int cn = wn * 32 + ni * 8 + (t << 1);
            float2 bb = *(const float2*)&bias[cn];
            if (r < M) {
                float2 o;
                o.x = c[mi][ni][0] + bb.x;
                o.y = c[mi][ni][1] + bb.y;
                *(float2*)&C[(size_t)r * N + cn] = o;
            }
            if (r + 8 < M) {
                float2 o;
                o.x = c[mi][ni][2] + bb.x;
                o.y = c[mi][ni][3] + bb.y;
                *(float2*)&C[(size_t)(r + 8) * N + cn] = o;
            }
        }
    }
}

// ---------------- propagation ----------------
// gather buffers hold hs = dinv * h (prescaled). Per node d:
//   agg = dinv_d * ( sum_{in-edges} hs[s] + hs[d] )
//   h_next = 0.9*agg + 0.1*h0;  store dinv_d*h_next (fp16) or h_next (fp32 final)
// warp/node; 16-lane half-warps each process one edge per step; lane (sub,c)
// accumulates cols 4c..4c+3; cross-half merge via shfl_xor(16).
__global__ void __launch_bounds__(256) k_prop(int src_id, int dst_id,
                                              float* __restrict__ ext_out)
{
    const __half2* hin = (src_id == 0) ? (const __half2*)g_h016
                       : (src_id == 1) ? (const __half2*)g_hA16
                                       : (const __half2*)g_hB16;
    __half2* hout16 = (dst_id == 1) ? (__half2*)g_hA16
                    : (dst_id == 2) ? (__half2*)g_hB16
                                    : nullptr;

    int node = (blockIdx.x * blockDim.x + threadIdx.x) >> 5;
    int lane = threadIdx.x & 31;
    if (node >= NN) return;
    int sub = lane >> 4;           // which edge of the pair
    int c   = lane & 15;           // column group: cols 4c..4c+3
    int beg = g_rowptr[node];
    int end = g_rowptr[node + 1];

    float a0 = 0.f, a1 = 0.f, a2 = 0.f, a3 = 0.f;
    for (int base = beg; base < end; base += 32) {
        int nb = end - base; if (nb > 32) nb = 32;
        int es = 0;
        if (lane < nb) es = g_esrc[base + lane];
#pragma unroll 4
        for (int j = 0; j < 16; j++) {
            int e = (j << 1) + sub;
            int s = __shfl_sync(0xffffffffu, es, e);
            if (e < nb) {
                const __half2* hp = hin + (size_t)s * (OUTC / 2) + (c << 1);
                uint2 raw = *(const uint2*)hp;
                float2 f0 = __half22float2(*(__half2*)&raw.x);
                float2 f1 = __half22float2(*(__half2*)&raw.y);
                a0 += f0.x; a1 += f0.y; a2 += f1.x; a3 += f1.y;
            }
            if ((j << 1) + 2 >= nb) break;
        }
    }
    // merge the two half-warp partial sums
    a0 += __shfl_xor_sync(0xffffffffu, a0, 16);
    a1 += __shfl_xor_sync(0xffffffffu, a1, 16);
    a2 += __shfl_xor_sync(0xffffffffu, a2, 16);
    a3 += __shfl_xor_sync(0xffffffffu, a3, 16);

    if (sub == 0) {
        float dv = g_dinv[node];
        // self loop (prescaled row)
        const __half2* sp = hin + (size_t)node * (OUTC / 2) + (c << 1);
        uint2 sraw = *(const uint2*)sp;
        float2 s0 = __half22float2(*(__half2*)&sraw.x);
        float2 s1 = __half22float2(*(__half2*)&sraw.y);
        a0 += s0.x; a1 += s0.y; a2 += s1.x; a3 += s1.y;

        float4 h0v = *(const float4*)(g_h0 + (size_t)node * OUTC + (c << 2));
        float o0 = 0.9f * dv * a0 + 0.1f * h0v.x;
        float o1 = 0.9f * dv * a1 + 0.1f * h0v.y;
        float o2 = 0.9f * dv * a2 + 0.1f * h0v.z;
        float o3 = 0.9f * dv * a3 + 0.1f * h0v.w;

        if (hout16) {
            __half2* op = hout16 + (size_t)node * (OUTC / 2) + (c << 1);
            uint2 ow;
            *(__half2*)&ow.x = __floats2half2_rn(dv * o0, dv * o1);
            *(__half2*)&ow.y = __floats2half2_rn(dv * o2, dv * o3);
            *(uint2*)op = ow;
        } else {
            *(float4*)(ext_out + (size_t)node * OUTC + (c << 2)) =
                make_float4(o0, o1, o2, o3);
        }
    }
}

// ---------------- launch ----------------
extern "C" void kernel_launch(void* const* d_in, const int* in_sizes, int n_in,
                              void* d_out, int out_size)
{
    const float* x  = (const float*)d_in[0];
    const int*   ei = (const int*)d_in[1];     // int32 (JAX x64 disabled)
    const float* W1 = (const float*)d_in[2];
    const float* b1 = (const float*)d_in[3];
    const float* W2 = (const float*)d_in[4];
    const float* b2 = (const float*)d_in[5];
    float* out = (float*)d_out;

    static cudaStream_t s2 = nullptr;
    static cudaEvent_t evFork = nullptr, evJoin = nullptr;
    if (s2 == nullptr) {
        cudaStreamCreateWithFlags(&s2, cudaStreamNonBlocking);
        cudaEventCreateWithFlags(&evFork, cudaEventDisableTiming);
        cudaEventCreateWithFlags(&evJoin, cudaEventDisableTiming);
    }

    // fork: graph preprocessing -> CSR by dst, on side stream
    cudaEventRecord(evFork, 0);
    cudaStreamWaitEvent(s2, evFork, 0);
    k_zero_cnt<<<(NN + 255) / 256, 256, 0, s2>>>();
    k_count<<<(NE + 255) / 256, 256, 0, s2>>>(ei);
    k_dinv<<<(NN + 255) / 256, 256, 0, s2>>>();
    k_scan1<<<NBLK_SCAN, 1024, 0, s2>>>();
    k_scan2<<<1, 32, 0, s2>>>();
    k_scan3<<<(NN + 255) / 256, 256, 0, s2>>>();
    k_fill<<<(NE + 255) / 256, 256, 0, s2>>>(ei);
    cudaEventRecord(evJoin, s2);

    // MLP encoder on main stream (independent of CSR build)
    dim3 g1((NN + 127) / 128, HID / 128);
    k_gemm1_tf32<<<g1, 256>>>(x, W1, b1, NN, HID, INC);
    dim3 g2((NN + 127) / 128, 1);
    k_gemm2_tf32<<<g2, 256>>>(W2, b2, NN, OUTC, HID);

    // join: prescale + propagation need both the CSR (dinv) and h0
    cudaStreamWaitEvent(0, evJoin, 0);
    k_prescale<<<(NN * (OUTC / 2) + 255) / 256, 256>>>();

    // 10 propagation iterations (ping-pong fp16; last writes fp32 d_out)
    int pgrid = (NN * 32 + 255) / 256;
    k_prop<<<pgrid, 256>>>(0, 1, out);
    k_prop<<<pgrid, 256>>>(1, 2, out);
    k_prop<<<pgrid, 256>>>(2, 1, out);
    k_prop<<<pgrid, 256>>>(1, 2, out);
    k_prop<<<pgrid, 256>>>(2, 1, out);
    k_prop<<<pgrid, 256>>>(1, 2, out);
    k_prop<<<pgrid, 256>>>(2, 1, out);
    k_prop<<<pgrid, 256>>>(1, 2, out);
    k_prop<<<pgrid, 256>>>(2, 1, out);
    k_prop<<<pgrid, 256>>>(1, 3, out);
    (void)in_sizes; (void)n_in; (void)out_size;
}